// round 13
// baseline (speedup 1.0000x reference)
#include <cuda_runtime.h>
#include <cuda_fp16.h>
#include <cstdint>

// ---------------------------------------------------------------------------
// GA (3,0,0) fused dense layer as one FP16 mma.sync GEMM (fp32 accumulate).
//   out[k*B+b, d] = sum_j s(k,j) * ( X[i(k,j)*B+b, :] @ W[:, j*D+d] ) + bias[k*D+d]
// M=16384, N=2048, K=16384.
// R13 = R12 (fp16 m16n8k16, 64x64 warp tiles, ldmatrix A + ldmatrix.trans B,
//       sign via pre-negated X pointer table) with QUAD processing:
//       4 k-tiles per wait+barrier on a 12-stage cp.async ring.
// ---------------------------------------------------------------------------

#define NTHREADS 128
#define BK 16
#define NKT 1024               // 16384 / BK
#define NQUADS 256
#define ASZB 4096              // A stage bytes: 128 rows x 16 k x 2B
#define BSZB 4096              // B stage bytes: 16 k x 128 n x 2B
#define STAGE_B (ASZB + BSZB)  // 8192 B
#define STAGES 12
#define SMEM_BYTES (STAGES * STAGE_B)   // 98304 B per CTA -> 2 CTAs/SM

// 64 MB scratch each: fp16 X, -X, W
__device__ __half Xh[16384 * 2048];
__device__ __half Xn[16384 * 2048];
__device__ __half Wh[2048 * 16384];

// ---------------- Cayley table (validated rounds 1-12) ----------------
__device__ __constant__ int c_kij[64] = {
    0,1,2,3,4,5,6,7,  1,0,4,5,2,3,7,6,  2,4,0,6,1,7,3,5,  3,5,6,0,7,1,2,4,
    4,2,1,7,0,6,5,3,  5,3,7,1,6,0,4,2,  6,7,3,2,5,4,0,1,  7,6,5,4,3,2,1,0};
__device__ __constant__ float c_sij[64] = {
    1.f, 1.f, 1.f, 1.f, 1.f, 1.f, 1.f, 1.f,
    1.f, 1.f, 1.f, 1.f, 1.f, 1.f, 1.f, 1.f,
    1.f,-1.f, 1.f, 1.f,-1.f,-1.f, 1.f,-1.f,
    1.f,-1.f,-1.f, 1.f, 1.f,-1.f,-1.f, 1.f,
    1.f,-1.f, 1.f, 1.f,-1.f,-1.f, 1.f,-1.f,
    1.f,-1.f,-1.f, 1.f, 1.f,-1.f,-1.f, 1.f,
    1.f, 1.f,-1.f, 1.f,-1.f, 1.f,-1.f,-1.f,
    1.f, 1.f,-1.f, 1.f,-1.f, 1.f,-1.f,-1.f};

__device__ __forceinline__ void gather_info(int kblk, int j, int& ib, float& sg) {
    int ibv = 0; float sv = 1.f;
#pragma unroll
    for (int ii = 0; ii < 8; ++ii) {
        bool m = (c_kij[ii * 8 + j] == kblk);
        ibv = m ? ii : ibv;
        sv  = m ? c_sij[ii * 8 + j] : sv;
    }
    ib = ibv; sg = sv;
}

__device__ __forceinline__ void mma_f16(float* d, const uint32_t* a,
                                        uint32_t b0, uint32_t b1) {
    asm volatile(
        "mma.sync.aligned.m16n8k16.row.col.f32.f16.f16.f32 "
        "{%0,%1,%2,%3}, {%4,%5,%6,%7}, {%8,%9}, {%0,%1,%2,%3};"
        : "+f"(d[0]), "+f"(d[1]), "+f"(d[2]), "+f"(d[3])
        : "r"(a[0]), "r"(a[1]), "r"(a[2]), "r"(a[3]), "r"(b0), "r"(b1));
}

__device__ __forceinline__ void ldsm4(uint32_t* r, uint32_t addr) {
    asm volatile("ldmatrix.sync.aligned.m8n8.x4.shared.b16 {%0,%1,%2,%3}, [%4];"
        : "=r"(r[0]), "=r"(r[1]), "=r"(r[2]), "=r"(r[3]) : "r"(addr));
}
__device__ __forceinline__ void ldsm4t(uint32_t* r, uint32_t addr) {
    asm volatile("ldmatrix.sync.aligned.m8n8.x4.trans.shared.b16 {%0,%1,%2,%3}, [%4];"
        : "=r"(r[0]), "=r"(r[1]), "=r"(r[2]), "=r"(r[3]) : "r"(addr));
}

__device__ __forceinline__ uint32_t smem_u32(const void* p) {
    uint32_t a;
    asm("{ .reg .u64 t; cvta.to.shared.u64 t, %1; cvt.u32.u64 %0, t; }" : "=r"(a) : "l"(p));
    return a;
}

__device__ __forceinline__ void cp16(uint32_t dst, const void* src) {
    asm volatile("cp.async.cg.shared.global [%0], [%1], 16;" :: "r"(dst), "l"(src) : "memory");
}
#define CP_COMMIT()  asm volatile("cp.async.commit_group;" ::: "memory")
#define CP_WAIT(n)   asm volatile("cp.async.wait_group %0;" :: "n"(n) : "memory")

// ---------------------------------------------------------------------------
// Preprocess: X/W -> fp16 (RN), plus negated X. 8 elements per thread.
__global__ __launch_bounds__(256)
void preconv_h(const float* __restrict__ X, const float* __restrict__ W)
{
    const size_t i = ((size_t)blockIdx.x * 256 + threadIdx.x) * 8;
    {
        float4 x0 = *reinterpret_cast<const float4*>(X + i);
        float4 x1 = *reinterpret_cast<const float4*>(X + i + 4);
        __half2 h[4];
        h[0] = __floats2half2_rn(x0.x, x0.y);
        h[1] = __floats2half2_rn(x0.z, x0.w);
        h[2] = __floats2half2_rn(x1.x, x1.y);
        h[3] = __floats2half2_rn(x1.z, x1.w);
        *reinterpret_cast<uint4*>(Xh + i) = *reinterpret_cast<uint4*>(h);
        __half2 hn[4];
#pragma unroll
        for (int t = 0; t < 4; ++t) hn[t] = __hneg2(h[t]);
        *reinterpret_cast<uint4*>(Xn + i) = *reinterpret_cast<uint4*>(hn);
    }
    {
        float4 w0 = *reinterpret_cast<const float4*>(W + i);
        float4 w1 = *reinterpret_cast<const float4*>(W + i + 4);
        __half2 h[4];
        h[0] = __floats2half2_rn(w0.x, w0.y);
        h[1] = __floats2half2_rn(w0.z, w0.w);
        h[2] = __floats2half2_rn(w1.x, w1.y);
        h[3] = __floats2half2_rn(w1.z, w1.w);
        *reinterpret_cast<uint4*>(Wh + i) = *reinterpret_cast<uint4*>(h);
    }
}

// ---------------------------------------------------------------------------
__global__ __launch_bounds__(NTHREADS, 2)
void ga_f16_mma2(const float* __restrict__ bias,  // [16384]
                 float* __restrict__ out)         // [16384, 2048]
{
    extern __shared__ uint32_t sm[];
    const uint32_t sb = smem_u32(sm);

    const int tid  = threadIdx.x;
    const int wid  = tid >> 5;
    const int lane = tid & 31;
    const int q    = lane & 3;
    const int g    = lane >> 2;
    const int wm   = wid >> 1;      // 0..1 (M warps, 64 rows each)
    const int wn   = wid & 1;       // 0..1 (N warps, 64 cols each)

    const int bn   = blockIdx.x;    // 0..15  N tiles (128 wide)
    const int bm   = blockIdx.y;    // 0..127 M tiles (128 tall)
    const int kblk = bm >> 4;       // output blade
    const int rloc = (bm & 15) * 128;

    // per-j A base pointer: sign baked in by selecting Xh vs Xn
    const __half* ApBase[8];
#pragma unroll
    for (int j = 0; j < 8; ++j) {
        int ib; float sg;
        gather_info(kblk, j, ib, sg);
        const __half* base = (sg > 0.f) ? Xh : Xn;
        ApBase[j] = base + ((size_t)(ib * 2048 + rloc)) * 2048;
    }

    float acc[4][8][4];
#pragma unroll
    for (int f = 0; f < 4; ++f)
#pragma unroll
        for (int n = 0; n < 8; ++n)
#pragma unroll
            for (int e = 0; e < 4; ++e) acc[f][n][e] = 0.f;

    // ---- ldmatrix per-lane precompute ----
    const int rowoff = (lane & 7) + ((lane >> 3) & 1) * 8;
    const int csel   = lane >> 4;                 // 0/1: second 16B chunk

    uint32_t aAddrOff[4];
#pragma unroll
    for (int f = 0; f < 4; ++f) {
        const int r = wm * 64 + f * 16 + rowoff;
        const int ch = csel ^ ((r >> 2) & 1);
        aAddrOff[f] = (uint32_t)(r * 32 + ch * 16);
    }
    const int kB = rowoff;
    uint32_t bAddrOff[4];
#pragma unroll
    for (int t = 0; t < 4; ++t) {
        const int c = wn * 8 + t * 2 + csel;
        bAddrOff[t] = (uint32_t)(kB * 256 + ((c ^ (kB & 7)) * 16));
    }

    // cp.async thread mappings
    const int a_m = tid >> 1;        // 0..63 (+64)
    const int a_c = tid & 1;
    const int b_c = tid & 15;
    const int b_k = tid >> 4;        // 0..7 (+8)

    auto issue_tile = [&](int kt) {
        const int s  = kt % STAGES;
        const int j  = kt >> 7;
        const int c0 = (kt & 127) * BK;
        const uint32_t As = sb + (uint32_t)(s * STAGE_B);
        const uint32_t Bs = As + ASZB;
        const __half* Ap = ApBase[j] + c0;
#pragma unroll
        for (int i = 0; i < 2; ++i) {
            const int m  = a_m + 64 * i;
            const int ch = a_c ^ ((m >> 2) & 1);
            cp16(As + (uint32_t)(m * 32 + ch * 16), Ap + (size_t)m * 2048 + a_c * 8);
        }
        const __half* Bp = Wh + (size_t)c0 * 16384 + (size_t)j * 2048 + bn * 128 + b_c * 8;
#pragma unroll
        for (int i = 0; i < 2; ++i) {
            const int k  = b_k + 8 * i;
            const int ch = b_c ^ (k & 7);
            cp16(Bs + (uint32_t)(k * 256 + ch * 16), Bp + (size_t)k * 16384);
        }
    };

    auto compute_tile = [&](int kt) {
        const int s = kt % STAGES;
        const uint32_t As = sb + (uint32_t)(s * STAGE_B);
        const uint32_t Bs = As + ASZB;
        uint32_t afr[4][4], bfr[4][4];
#pragma unroll
        for (int f = 0; f < 4; ++f) ldsm4(afr[f], As + aAddrOff[f]);
#pragma unroll
        for (int t = 0; t < 4; ++t) ldsm4t(bfr[t], Bs + bAddrOff[t]);
        // bfr[t]: r0,r1 = (b0,b1) for nf=2t ; r2,r3 = (b0,b1) for nf=2t+1
#pragma unroll
        for (int f = 0; f < 4; ++f)
#pragma unroll
            for (int t = 0; t < 4; ++t) {
                mma_f16(acc[f][2 * t    ], afr[f], bfr[t][0], bfr[t][1]);
                mma_f16(acc[f][2 * t + 1], afr[f], bfr[t][2], bfr[t][3]);
            }
    };

    // prologue: quads 0 and 1 (tiles 0..7), one commit group per quad
    issue_tile(0); issue_tile(1); issue_tile(2); issue_tile(3); CP_COMMIT();
    issue_tile(4); issue_tile(5); issue_tile(6); issue_tile(7); CP_COMMIT();

    for (int p = 0; p < NQUADS; ++p) {
        if (p < NQUADS - 1) { CP_WAIT(1); } else { CP_WAIT(0); }
        __syncthreads();     // single barrier per quad; protects stage reuse

        if (p + 2 < NQUADS) {
            issue_tile(4 * p + 8);
            issue_tile(4 * p + 9);
            issue_tile(4 * p + 10);
            issue_tile(4 * p + 11);
            CP_COMMIT();
        }

        compute_tile(4 * p);
        compute_tile(4 * p + 1);
        compute_tile(4 * p + 2);
        compute_tile(4 * p + 3);
        // no trailing barrier: next iteration's writes target quad p-1's
        // stages, which every warp finished before this iteration's barrier.
    }

    // ---- epilogue: add blade bias, store ----
    const int ccol = bn * 128 + wn * 64;
    const float* bp = bias + (size_t)kblk * 2048 + ccol;

#pragma unroll
    for (int nf = 0; nf < 8; ++nf) {
        const int cn = nf * 8 + 2 * q;
        const float b0 = bp[cn], b1 = bp[cn + 1];
#pragma unroll
        for (int f = 0; f < 4; ++f) {
            const int r0 = bm * 128 + wm * 64 + f * 16 + g;
            float2 lo  = make_float2(acc[f][nf][0] + b0, acc[f][nf][1] + b1);
            float2 hi2 = make_float2(acc[f][nf][2] + b0, acc[f][nf][3] + b1);
            *reinterpret_cast<float2*>(out + (size_t)r0 * 2048 + ccol + cn)       = lo;
            *reinterpret_cast<float2*>(out + (size_t)(r0 + 8) * 2048 + ccol + cn) = hi2;
        }
    }
}

extern "C" void kernel_launch(void* const* d_in, const int* in_sizes, int n_in,
                              void* d_out, int out_size)
{
    const float* X    = (const float*)d_in[0];
    const float* W    = (const float*)d_in[1];
    const float* bias = (const float*)d_in[2];
    float* out        = (float*)d_out;

    preconv_h<<<16384, 256>>>(X, W);

    cudaFuncSetAttribute(ga_f16_mma2, cudaFuncAttributeMaxDynamicSharedMemorySize, SMEM_BYTES);
    dim3 grid(16, 128);
    ga_f16_mma2<<<grid, NTHREADS, SMEM_BYTES>>>(bias, out);
}

// round 14
// speedup vs baseline: 1.3029x; 1.3029x over previous
#include <cuda_runtime.h>
#include <cuda_fp16.h>
#include <cstdint>

// ---------------------------------------------------------------------------
// GA (3,0,0) fused dense layer as one FP16 mma.sync GEMM (fp32 accumulate).
//   out[k*B+b, d] = sum_j s(k,j) * ( X[i(k,j)*B+b, :] @ W[:, j*D+d] ) + bias[k*D+d]
// M=16384, N=2048, K=16384.
// R14 = R12 (best: fp16 m16n8k16, 64x64 warp tiles, ldmatrix A +
//       ldmatrix.trans B, pair processing, sign via pre-negated X) with a
//       DEEPER ring: 8 stages, wait_group(2), prefetch distance 3 pairs.
// ---------------------------------------------------------------------------

#define NTHREADS 128
#define BK 16
#define NKT 1024               // 16384 / BK
#define NPAIRS 512
#define ASZB 4096              // A stage bytes: 128 rows x 16 k x 2B
#define BSZB 4096              // B stage bytes: 16 k x 128 n x 2B
#define STAGE_B (ASZB + BSZB)  // 8192 B
#define STAGES 8
#define SMEM_BYTES (STAGES * STAGE_B)   // 65536 B per CTA -> 2 CTAs/SM

// 64 MB scratch each: fp16 X, -X, W
__device__ __half Xh[16384 * 2048];
__device__ __half Xn[16384 * 2048];
__device__ __half Wh[2048 * 16384];

// ---------------- Cayley table (validated rounds 1-13) ----------------
__device__ __constant__ int c_kij[64] = {
    0,1,2,3,4,5,6,7,  1,0,4,5,2,3,7,6,  2,4,0,6,1,7,3,5,  3,5,6,0,7,1,2,4,
    4,2,1,7,0,6,5,3,  5,3,7,1,6,0,4,2,  6,7,3,2,5,4,0,1,  7,6,5,4,3,2,1,0};
__device__ __constant__ float c_sij[64] = {
    1.f, 1.f, 1.f, 1.f, 1.f, 1.f, 1.f, 1.f,
    1.f, 1.f, 1.f, 1.f, 1.f, 1.f, 1.f, 1.f,
    1.f,-1.f, 1.f, 1.f,-1.f,-1.f, 1.f,-1.f,
    1.f,-1.f,-1.f, 1.f, 1.f,-1.f,-1.f, 1.f,
    1.f,-1.f, 1.f, 1.f,-1.f,-1.f, 1.f,-1.f,
    1.f,-1.f,-1.f, 1.f, 1.f,-1.f,-1.f, 1.f,
    1.f, 1.f,-1.f, 1.f,-1.f, 1.f,-1.f,-1.f,
    1.f, 1.f,-1.f, 1.f,-1.f, 1.f,-1.f,-1.f};

__device__ __forceinline__ void gather_info(int kblk, int j, int& ib, float& sg) {
    int ibv = 0; float sv = 1.f;
#pragma unroll
    for (int ii = 0; ii < 8; ++ii) {
        bool m = (c_kij[ii * 8 + j] == kblk);
        ibv = m ? ii : ibv;
        sv  = m ? c_sij[ii * 8 + j] : sv;
    }
    ib = ibv; sg = sv;
}

__device__ __forceinline__ void mma_f16(float* d, const uint32_t* a,
                                        uint32_t b0, uint32_t b1) {
    asm volatile(
        "mma.sync.aligned.m16n8k16.row.col.f32.f16.f16.f32 "
        "{%0,%1,%2,%3}, {%4,%5,%6,%7}, {%8,%9}, {%0,%1,%2,%3};"
        : "+f"(d[0]), "+f"(d[1]), "+f"(d[2]), "+f"(d[3])
        : "r"(a[0]), "r"(a[1]), "r"(a[2]), "r"(a[3]), "r"(b0), "r"(b1));
}

__device__ __forceinline__ void ldsm4(uint32_t* r, uint32_t addr) {
    asm volatile("ldmatrix.sync.aligned.m8n8.x4.shared.b16 {%0,%1,%2,%3}, [%4];"
        : "=r"(r[0]), "=r"(r[1]), "=r"(r[2]), "=r"(r[3]) : "r"(addr));
}
__device__ __forceinline__ void ldsm4t(uint32_t* r, uint32_t addr) {
    asm volatile("ldmatrix.sync.aligned.m8n8.x4.trans.shared.b16 {%0,%1,%2,%3}, [%4];"
        : "=r"(r[0]), "=r"(r[1]), "=r"(r[2]), "=r"(r[3]) : "r"(addr));
}

__device__ __forceinline__ uint32_t smem_u32(const void* p) {
    uint32_t a;
    asm("{ .reg .u64 t; cvta.to.shared.u64 t, %1; cvt.u32.u64 %0, t; }" : "=r"(a) : "l"(p));
    return a;
}

__device__ __forceinline__ void cp16(uint32_t dst, const void* src) {
    asm volatile("cp.async.cg.shared.global [%0], [%1], 16;" :: "r"(dst), "l"(src) : "memory");
}
#define CP_COMMIT()  asm volatile("cp.async.commit_group;" ::: "memory")
#define CP_WAIT(n)   asm volatile("cp.async.wait_group %0;" :: "n"(n) : "memory")

// ---------------------------------------------------------------------------
// Preprocess: X/W -> fp16 (RN), plus negated X. 8 elements per thread.
__global__ __launch_bounds__(256)
void preconv_h(const float* __restrict__ X, const float* __restrict__ W)
{
    const size_t i = ((size_t)blockIdx.x * 256 + threadIdx.x) * 8;
    {
        float4 x0 = *reinterpret_cast<const float4*>(X + i);
        float4 x1 = *reinterpret_cast<const float4*>(X + i + 4);
        __half2 h[4];
        h[0] = __floats2half2_rn(x0.x, x0.y);
        h[1] = __floats2half2_rn(x0.z, x0.w);
        h[2] = __floats2half2_rn(x1.x, x1.y);
        h[3] = __floats2half2_rn(x1.z, x1.w);
        *reinterpret_cast<uint4*>(Xh + i) = *reinterpret_cast<uint4*>(h);
        __half2 hn[4];
#pragma unroll
        for (int t = 0; t < 4; ++t) hn[t] = __hneg2(h[t]);
        *reinterpret_cast<uint4*>(Xn + i) = *reinterpret_cast<uint4*>(hn);
    }
    {
        float4 w0 = *reinterpret_cast<const float4*>(W + i);
        float4 w1 = *reinterpret_cast<const float4*>(W + i + 4);
        __half2 h[4];
        h[0] = __floats2half2_rn(w0.x, w0.y);
        h[1] = __floats2half2_rn(w0.z, w0.w);
        h[2] = __floats2half2_rn(w1.x, w1.y);
        h[3] = __floats2half2_rn(w1.z, w1.w);
        *reinterpret_cast<uint4*>(Wh + i) = *reinterpret_cast<uint4*>(h);
    }
}

// ---------------------------------------------------------------------------
__global__ __launch_bounds__(NTHREADS, 2)
void ga_f16_mma3(const float* __restrict__ bias,  // [16384]
                 float* __restrict__ out)         // [16384, 2048]
{
    extern __shared__ uint32_t sm[];
    const uint32_t sb = smem_u32(sm);

    const int tid  = threadIdx.x;
    const int wid  = tid >> 5;
    const int lane = tid & 31;
    const int q    = lane & 3;
    const int g    = lane >> 2;
    const int wm   = wid >> 1;      // 0..1 (M warps, 64 rows each)
    const int wn   = wid & 1;       // 0..1 (N warps, 64 cols each)

    const int bn   = blockIdx.x;    // 0..15  N tiles (128 wide)
    const int bm   = blockIdx.y;    // 0..127 M tiles (128 tall)
    const int kblk = bm >> 4;       // output blade
    const int rloc = (bm & 15) * 128;

    // per-j A base pointer: sign baked in by selecting Xh vs Xn
    const __half* ApBase[8];
#pragma unroll
    for (int j = 0; j < 8; ++j) {
        int ib; float sg;
        gather_info(kblk, j, ib, sg);
        const __half* base = (sg > 0.f) ? Xh : Xn;
        ApBase[j] = base + ((size_t)(ib * 2048 + rloc)) * 2048;
    }

    float acc[4][8][4];
#pragma unroll
    for (int f = 0; f < 4; ++f)
#pragma unroll
        for (int n = 0; n < 8; ++n)
#pragma unroll
            for (int e = 0; e < 4; ++e) acc[f][n][e] = 0.f;

    // ---- ldmatrix per-lane precompute ----
    const int rowoff = (lane & 7) + ((lane >> 3) & 1) * 8;
    const int csel   = lane >> 4;                 // 0/1: second 16B chunk

    uint32_t aAddrOff[4];
#pragma unroll
    for (int f = 0; f < 4; ++f) {
        const int r = wm * 64 + f * 16 + rowoff;
        const int ch = csel ^ ((r >> 2) & 1);
        aAddrOff[f] = (uint32_t)(r * 32 + ch * 16);
    }
    const int kB = rowoff;
    uint32_t bAddrOff[4];
#pragma unroll
    for (int t = 0; t < 4; ++t) {
        const int c = wn * 8 + t * 2 + csel;
        bAddrOff[t] = (uint32_t)(kB * 256 + ((c ^ (kB & 7)) * 16));
    }

    // cp.async thread mappings
    const int a_m = tid >> 1;        // 0..63 (+64)
    const int a_c = tid & 1;
    const int b_c = tid & 15;
    const int b_k = tid >> 4;        // 0..7 (+8)

    auto issue_tile = [&](int kt) {
        const int s  = kt & (STAGES - 1);
        const int j  = kt >> 7;
        const int c0 = (kt & 127) * BK;
        const uint32_t As = sb + (uint32_t)(s * STAGE_B);
        const uint32_t Bs = As + ASZB;
        const __half* Ap = ApBase[j] + c0;
#pragma unroll
        for (int i = 0; i < 2; ++i) {
            const int m  = a_m + 64 * i;
            const int ch = a_c ^ ((m >> 2) & 1);
            cp16(As + (uint32_t)(m * 32 + ch * 16), Ap + (size_t)m * 2048 + a_c * 8);
        }
        const __half* Bp = Wh + (size_t)c0 * 16384 + (size_t)j * 2048 + bn * 128 + b_c * 8;
#pragma unroll
        for (int i = 0; i < 2; ++i) {
            const int k  = b_k + 8 * i;
            const int ch = b_c ^ (k & 7);
            cp16(Bs + (uint32_t)(k * 256 + ch * 16), Bp + (size_t)k * 16384);
        }
    };

    auto compute_tile = [&](int kt) {
        const int s = kt & (STAGES - 1);
        const uint32_t As = sb + (uint32_t)(s * STAGE_B);
        const uint32_t Bs = As + ASZB;
        uint32_t afr[4][4], bfr[4][4];
#pragma unroll
        for (int f = 0; f < 4; ++f) ldsm4(afr[f], As + aAddrOff[f]);
#pragma unroll
        for (int t = 0; t < 4; ++t) ldsm4t(bfr[t], Bs + bAddrOff[t]);
        // bfr[t]: r0,r1 = (b0,b1) for nf=2t ; r2,r3 = (b0,b1) for nf=2t+1
#pragma unroll
        for (int f = 0; f < 4; ++f)
#pragma unroll
            for (int t = 0; t < 4; ++t) {
                mma_f16(acc[f][2 * t    ], afr[f], bfr[t][0], bfr[t][1]);
                mma_f16(acc[f][2 * t + 1], afr[f], bfr[t][2], bfr[t][3]);
            }
    };

    // prologue: pairs 0..2 (tiles 0..5), one commit group per pair
    issue_tile(0); issue_tile(1); CP_COMMIT();
    issue_tile(2); issue_tile(3); CP_COMMIT();
    issue_tile(4); issue_tile(5); CP_COMMIT();

    for (int p = 0; p < NPAIRS; ++p) {
        // wait until pair p has landed (up to 2 newer groups may remain)
        if (p < NPAIRS - 2)      { CP_WAIT(2); }
        else if (p == NPAIRS - 2){ CP_WAIT(1); }
        else                     { CP_WAIT(0); }
        __syncthreads();     // single barrier per pair; protects stage reuse

        if (p + 3 < NPAIRS) {
            issue_tile(2 * p + 6);
            issue_tile(2 * p + 7);
            CP_COMMIT();
        }

        compute_tile(2 * p);
        compute_tile(2 * p + 1);
        // no trailing barrier: this iteration's issue writes pair p+3's
        // stages == (mod 8) pair p-1's stages, consumed last iteration and
        // protected by this iteration's barrier.
    }

    // ---- epilogue: add blade bias, store ----
    const int ccol = bn * 128 + wn * 64;
    const float* bp = bias + (size_t)kblk * 2048 + ccol;

#pragma unroll
    for (int nf = 0; nf < 8; ++nf) {
        const int cn = nf * 8 + 2 * q;
        const float b0 = bp[cn], b1 = bp[cn + 1];
#pragma unroll
        for (int f = 0; f < 4; ++f) {
            const int r0 = bm * 128 + wm * 64 + f * 16 + g;
            float2 lo  = make_float2(acc[f][nf][0] + b0, acc[f][nf][1] + b1);
            float2 hi2 = make_float2(acc[f][nf][2] + b0, acc[f][nf][3] + b1);
            *reinterpret_cast<float2*>(out + (size_t)r0 * 2048 + ccol + cn)       = lo;
            *reinterpret_cast<float2*>(out + (size_t)(r0 + 8) * 2048 + ccol + cn) = hi2;
        }
    }
}

extern "C" void kernel_launch(void* const* d_in, const int* in_sizes, int n_in,
                              void* d_out, int out_size)
{
    const float* X    = (const float*)d_in[0];
    const float* W    = (const float*)d_in[1];
    const float* bias = (const float*)d_in[2];
    float* out        = (float*)d_out;

    preconv_h<<<16384, 256>>>(X, W);

    cudaFuncSetAttribute(ga_f16_mma3, cudaFuncAttributeMaxDynamicSharedMemorySize, SMEM_BYTES);
    dim3 grid(16, 128);
    ga_f16_mma3<<<grid, NTHREADS, SMEM_BYTES>>>(bias, out);
}